// round 16
// baseline (speedup 1.0000x reference)
#include <cuda_runtime.h>
#include <cuda_fp16.h>
#include <math.h>
#include <stdint.h>

#define EMB 64
#define HID 128
#define NN  50000
#define NE  800000
#define NQ  64
#define NTILES (NE / 128)

// ---------------- scratch (static device globals; no allocation) ----------------
__device__ float   g_Aq[NQ * EMB];        // (qe@Wq+bq) @ W1a
__device__ float   g_biasAB[EMB];         // b1 + be@W1b + br@W1c
__device__ float   g_biasC [EMB];         // be@W1d
// fp16 node tables in gather-native layout: row n has 32 half2; position tig*8+nt
__device__ __half2 g_ABnh[NN * 32];
__device__ __half2 g_Cnh [NN * 32];
__device__ __half2 g_Mt  [EMB * 32];      // Wr@W1c as [n][k] fp16, k-contiguous (64 rows x 128B)
__device__ __half2 g_W2t [HID * 32];      // W2 as [n][k] fp16, k-contiguous (128 rows x 128B)
__device__ __half2 g_MbMdt[2 * EMB * 32]; // permuted layout for node kernel (rows 0..63 Mb, 64..127 Md)

// ---------------- helpers ----------------
__device__ __forceinline__ void mma_f16(float& c0, float& c1, float& c2, float& c3,
                                        uint32_t a0, uint32_t a1, uint32_t a2, uint32_t a3,
                                        uint32_t b0, uint32_t b1) {
    asm volatile("mma.sync.aligned.m16n8k16.row.col.f32.f16.f16.f32 "
                 "{%0,%1,%2,%3}, {%4,%5,%6,%7}, {%8,%9}, {%0,%1,%2,%3};\n"
                 : "+f"(c0), "+f"(c1), "+f"(c2), "+f"(c3)
                 : "r"(a0), "r"(a1), "r"(a2), "r"(a3), "r"(b0), "r"(b1));
}
__device__ __forceinline__ void ldsm_x4(uint32_t& r0, uint32_t& r1, uint32_t& r2, uint32_t& r3,
                                        uint32_t addr) {
    asm volatile("ldmatrix.sync.aligned.m8n8.x4.shared.b16 {%0,%1,%2,%3}, [%4];"
                 : "=r"(r0), "=r"(r1), "=r"(r2), "=r"(r3) : "r"(addr));
}
// permuted position for node-kernel layout
__device__ __forceinline__ int permp(int j) {
    int c = j >> 3, p = j & 7;
    return (c << 3) | ((p & 3) << 1) | (p >> 2);
}

// ---------------- fused prep kernel: 42 fully-parallel blocks, ONE launch ----------------
// b==0       : Aq = (qe@Wq+bq)@W1a (two-stage in-block)
// b in 1..8  : g_Mt   (2048 half2)   — each elem = two 64-deep dots of Wr x W1c
// b in 9..24 : g_MbMdt(4096 half2)   — permuted node layout, dots of We x W1b/W1d
// b in 25..40: g_W2t  (4096 half2)   — pure transpose of W2
// b==41      : biasAB / biasC
__global__ void prep_kernel(const float* __restrict__ qe,
                            const float* __restrict__ Wq, const float* __restrict__ bq,
                            const float* __restrict__ We, const float* __restrict__ be,
                            const float* __restrict__ Wr, const float* __restrict__ br,
                            const float* __restrict__ W1, const float* __restrict__ b1,
                            const float* __restrict__ W2) {
    __shared__ float sP[EMB * EMB];
    __shared__ float sbq[EMB];
    int b = blockIdx.x, t = threadIdx.x;

    if (b == 0) {
        // T = Wq @ W1a ; sbq = bq @ W1a ; Aq = qe @ T + sbq
        #pragma unroll
        for (int j = 0; j < 16; j++) {
            int idx = t + 256 * j;
            int k = idx >> 6, n = idx & 63;
            float s = 0.f;
            #pragma unroll 8
            for (int i = 0; i < EMB; i++) s += Wq[k * EMB + i] * W1[i * EMB + n];
            sP[idx] = s;
        }
        if (t < 64) {
            float s = 0.f;
            #pragma unroll 8
            for (int i = 0; i < EMB; i++) s += bq[i] * W1[i * EMB + t];
            sbq[t] = s;
        }
        __syncthreads();
        #pragma unroll
        for (int j = 0; j < 16; j++) {
            int idx = t + 256 * j;
            int q = idx >> 6, n = idx & 63;
            float s = sbq[n];
            #pragma unroll 8
            for (int k = 0; k < EMB; k++) s += qe[q * EMB + k] * sP[k * EMB + n];
            g_Aq[idx] = s;
        }
    } else if (b <= 8) {
        // g_Mt[n][kp] = ( M[2kp][n], M[2kp+1][n] ),  M[k][j] = sum_i Wr[k,i] W1[128+i, j]
        int idx = (b - 1) * 256 + t;          // 0..2047
        int n = idx >> 5, kp = idx & 31;
        float v0 = 0.f, v1 = 0.f;
        #pragma unroll 8
        for (int i = 0; i < EMB; i++) {
            float wj = W1[(128 + i) * EMB + n];
            v0 += Wr[(2 * kp)     * EMB + i] * wj;
            v1 += Wr[(2 * kp + 1) * EMB + i] * wj;
        }
        g_Mt[idx] = __floats2half2_rn(v0, v1);
    } else if (b <= 24) {
        // g_MbMdt permuted: rows 0..63 Mb (yoff 64), rows 64..127 Md (yoff 192)
        int idx = (b - 9) * 256 + t;          // 0..4095
        int n = idx >> 5, pos = idx & 31;
        int c = pos >> 3, q = pos & 7;
        int p = (q >> 1) + ((q & 1) << 2);
        int k0 = (c << 4) + (p << 1);
        int nn = n & 63;
        int yoff = (n < 64) ? 64 : 192;
        float v0 = 0.f, v1 = 0.f;
        #pragma unroll 8
        for (int i = 0; i < EMB; i++) {
            float wj = W1[(yoff + i) * EMB + nn];
            v0 += We[k0       * EMB + i] * wj;
            v1 += We[(k0 + 1) * EMB + i] * wj;
        }
        g_MbMdt[idx] = __floats2half2_rn(v0, v1);
    } else if (b <= 40) {
        // g_W2t[n][kp] = ( W2[2kp][n], W2[2kp+1][n] )
        int idx = (b - 25) * 256 + t;         // 0..4095
        int n = idx >> 5, kp = idx & 31;
        g_W2t[idx] = __floats2half2_rn(W2[(2 * kp) * HID + n], W2[(2 * kp + 1) * HID + n]);
    } else {
        if (t < 64) {
            float sAB = b1[t], sC = 0.f;
            #pragma unroll 8
            for (int i = 0; i < EMB; i++) {
                sAB += be[i] * W1[(64 + i) * EMB + t] + br[i] * W1[(128 + i) * EMB + t];
                sC  += be[i] * W1[(192 + i) * EMB + t];
            }
            g_biasAB[t] = sAB;
            g_biasC[t]  = sC;
        }
    }
}

// ---------------- node kernel: fp16 mma, two 32-acc passes (3 blocks/SM) ----------------
__global__ __launch_bounds__(256, 3) void node_mma_kernel(const float* __restrict__ nodeEmb,
                                                          const int*   __restrict__ nodeBatch) {
    __shared__ __half2 sNE[128 * 40];
    __shared__ __half2 sW [128 * 40];

    int t = threadIdx.x;
    int n0 = blockIdx.x * 128;

    for (int i = t; i < 4096; i += 256) sW[(i >> 5) * 40 + (i & 31)] = g_MbMdt[i];
    #pragma unroll
    for (int j = 0; j < 8; j++) {
        int i = t + 256 * j;
        int r = i >> 4, q = i & 15;
        int n = n0 + r;
        float4 v = (n < NN) ? ((const float4*)nodeEmb)[(size_t)n * 16 + q]
                            : make_float4(0.f, 0.f, 0.f, 0.f);
        __half2* row = &sNE[r * 40];
        row[permp(2 * q)]     = __floats2half2_rn(v.x, v.y);
        row[permp(2 * q + 1)] = __floats2half2_rn(v.z, v.w);
    }
    __syncthreads();

    int w = t >> 5, lane = t & 31;
    int g = lane >> 2, tig = lane & 3;
    int rA = w * 16 + g;
    int tig2 = tig << 1;

    const __half2* eeLo = &sNE[rA * 40 + tig2];
    const __half2* eeHi = &sNE[(rA + 8) * 40 + tig2];

    int nlo = n0 + rA, nhi = n0 + rA + 8;
    int qlo = (nlo < NN) ? nodeBatch[nlo] : 0;
    int qhi = (nhi < NN) ? nodeBatch[nhi] : 0;

    // ---- pass A: ABn = ne@Mb + biasAB + Aq ----
    {
        float acc[32];
        #pragma unroll
        for (int j = 0; j < 32; j++) acc[j] = 0.f;
        #pragma unroll
        for (int kt = 0; kt < 4; kt++) {
            int base = kt * 8;
            uint2 va = *(const uint2*)(eeLo + base);
            uint2 vb = *(const uint2*)(eeHi + base);
            #pragma unroll
            for (int nt = 0; nt < 8; nt++) {
                uint2 wb = *(const uint2*)(&sW[(nt * 8 + g) * 40 + base + tig2]);
                mma_f16(acc[nt*4], acc[nt*4+1], acc[nt*4+2], acc[nt*4+3],
                        va.x, vb.x, va.y, vb.y, wb.x, wb.y);
            }
        }
        __half2 blo[8], bhi[8];
        #pragma unroll
        for (int nt = 0; nt < 8; nt++) {
            int c = nt * 8 + tig2;
            float bA0 = g_biasAB[c], bA1 = g_biasAB[c + 1];
            blo[nt] = __floats2half2_rn(acc[nt*4+0] + bA0 + g_Aq[qlo * 64 + c],
                                        acc[nt*4+1] + bA1 + g_Aq[qlo * 64 + c + 1]);
            bhi[nt] = __floats2half2_rn(acc[nt*4+2] + bA0 + g_Aq[qhi * 64 + c],
                                        acc[nt*4+3] + bA1 + g_Aq[qhi * 64 + c + 1]);
        }
        if (nlo < NN) {
            __half2* dA = g_ABnh + (size_t)nlo * 32 + tig * 8;
            *(uint4*)(dA) = *(uint4*)(blo); *(uint4*)(dA + 4) = *(uint4*)(blo + 4);
        }
        if (nhi < NN) {
            __half2* dA = g_ABnh + (size_t)nhi * 32 + tig * 8;
            *(uint4*)(dA) = *(uint4*)(bhi); *(uint4*)(dA + 4) = *(uint4*)(bhi + 4);
        }
    }
    // ---- pass B: Cn = ne@Md + biasC ----
    {
        float acc[32];
        #pragma unroll
        for (int j = 0; j < 32; j++) acc[j] = 0.f;
        #pragma unroll
        for (int kt = 0; kt < 4; kt++) {
            int base = kt * 8;
            uint2 va = *(const uint2*)(eeLo + base);
            uint2 vb = *(const uint2*)(eeHi + base);
            #pragma unroll
            for (int nt = 0; nt < 8; nt++) {
                uint2 wb = *(const uint2*)(&sW[(64 + nt * 8 + g) * 40 + base + tig2]);
                mma_f16(acc[nt*4], acc[nt*4+1], acc[nt*4+2], acc[nt*4+3],
                        va.x, vb.x, va.y, vb.y, wb.x, wb.y);
            }
        }
        __half2 blo[8], bhi[8];
        #pragma unroll
        for (int nt = 0; nt < 8; nt++) {
            int c = nt * 8 + tig2;
            float bC0 = g_biasC[c], bC1 = g_biasC[c + 1];
            blo[nt] = __floats2half2_rn(acc[nt*4+0] + bC0, acc[nt*4+1] + bC1);
            bhi[nt] = __floats2half2_rn(acc[nt*4+2] + bC0, acc[nt*4+3] + bC1);
        }
        if (nlo < NN) {
            __half2* dC = g_Cnh + (size_t)nlo * 32 + tig * 8;
            *(uint4*)(dC) = *(uint4*)(blo); *(uint4*)(dC + 4) = *(uint4*)(blo + 4);
        }
        if (nhi < NN) {
            __half2* dC = g_Cnh + (size_t)nhi * 32 + tig * 8;
            *(uint4*)(dC) = *(uint4*)(bhi); *(uint4*)(dC + 4) = *(uint4*)(bhi + 4);
        }
    }
}

// ---------------- persistent edge kernel: SW128 + ldmatrix fragment path ----------------
// smem bytes: sEE 0..16384 (128 rows x 128B, swizzled; EE tile then H)
//             sM  16384..24576 | sW2 24576..40960 | sWh/sb2/sHT tail
#define OFF_M   16384
#define OFF_W2  24576
#define OFF_WHb 40960
#define SME_BYTES (40960 + 512 + 512 + 1024)

__global__ __launch_bounds__(256, 2) void edge_kernel(const float* __restrict__ edgeEmb,
                                                      const int*   __restrict__ edgeIndex,
                                                      const float* __restrict__ b2,
                                                      const float* __restrict__ Wh,
                                                      const float* __restrict__ bh,
                                                      float* __restrict__ out) {
    extern __shared__ char smE[];
    uint32_t sbs = (uint32_t)__cvta_generic_to_shared(smE);
    float* sWh = (float*)(smE + OFF_WHb);
    float* sb2 = (float*)(smE + OFF_WHb + 512);
    int*   sHT = (int*)  (smE + OFF_WHb + 1024);

    int t = threadIdx.x;

    // ---- copy weights into swizzled smem ONCE ----
    {
        const uint4* gm = (const uint4*)g_Mt;
        uint4* dm = (uint4*)(smE + OFF_M);
        for (int i = t; i < 512; i += 256) {
            int d = (i & ~7) | ((i & 7) ^ ((i >> 3) & 7));
            dm[d] = gm[i];
        }
        const uint4* gw = (const uint4*)g_W2t;
        uint4* dw = (uint4*)(smE + OFF_W2);
        for (int i = t; i < 1024; i += 256) {
            int d = (i & ~7) | ((i & 7) ^ ((i >> 3) & 7));
            dw[d] = gw[i];
        }
    }
    if (t < 128) { sWh[t] = Wh[t]; sb2[t] = b2[t]; }
    float bhv = bh[0];

    int w = t >> 5, lane = t & 31;
    int g = lane >> 2, tig = lane & 3;
    int rA = w * 16 + g;
    int tig2 = tig << 1;

    // staging offsets: thread's 8 chunks -> swizzled 8B slots
    int soff[8];
    #pragma unroll
    for (int j = 0; j < 8; j++) {
        int i = t + 256 * j;
        int r = i >> 4, q = i & 15;
        soff[j] = (r * 8 + ((q >> 1) ^ (r & 7))) * 16 + (q & 1) * 8;
    }

    // ldmatrix per-thread address components
    int laneRowA = w * 16 + (lane & 7) + ((lane >> 3) & 1) * 8;
    int c01   = (lane >> 4) & 1;
    int maskA = laneRowA & 7;
    uint32_t baseA = sbs + laneRowA * 128;
    int rBl   = ((lane >> 4) << 3) + (lane & 7);
    int segB  = (lane >> 3) & 1;
    int maskB = rBl & 7;
    uint32_t baseB1 = sbs + OFF_M  + rBl * 128;
    uint32_t baseB2 = sbs + OFF_W2 + rBl * 128;

    // H writeback pointers
    char* hp1 = smE + rA * 128 + tig * 4;
    char* hp2 = smE + (rA + 8) * 128 + tig * 4;

    // ---- prefetch first tile ----
    float4 pv[8];
    int ih = 0, itl = 0;
    int tile = blockIdx.x;
    if (tile < NTILES) {
        int e0 = tile * 128;
        #pragma unroll
        for (int j = 0; j < 8; j++) {
            int i = t + 256 * j;
            pv[j] = ((const float4*)edgeEmb)[(size_t)(e0 + (i >> 4)) * 16 + (i & 15)];
        }
        if (t < 128) { ih = edgeIndex[e0 + t]; itl = edgeIndex[NE + e0 + t]; }
    }

    for (; tile < NTILES; tile += gridDim.x) {
        int e0 = tile * 128;
        __syncthreads();                 // prior tile's smem reads done
        #pragma unroll
        for (int j = 0; j < 8; j++) {
            __half2 h0 = __floats2half2_rn(pv[j].x, pv[j].y);
            __half2 h1 = __floats2half2_rn(pv[j].z, pv[j].w);
            uint2 hv;
            hv.x = *(uint32_t*)&h0;
            hv.y = *(uint32_t*)&h1;
            *(uint2*)(smE + soff[j]) = hv;
        }
        if (t < 128) { sHT[t] = ih; sHT[128 + t] = itl; }
        __syncthreads();                 // tile visible

        // ---- issue node-table gathers (consumed AFTER stage 1) ----
        int h0i = sHT[rA],     t0i = sHT[128 + rA];
        int h1i = sHT[rA + 8], t1i = sHT[128 + rA + 8];
        uint32_t gA0[8], gC0[8], gA1[8], gC1[8];
        {
            const uint4* pA0 = (const uint4*)(g_ABnh + (size_t)h0i * 32 + tig * 8);
            const uint4* pC0 = (const uint4*)(g_Cnh  + (size_t)t0i * 32 + tig * 8);
            const uint4* pA1 = (const uint4*)(g_ABnh + (size_t)h1i * 32 + tig * 8);
            const uint4* pC1 = (const uint4*)(g_Cnh  + (size_t)t1i * 32 + tig * 8);
            *(uint4*)(gA0) = pA0[0]; *(uint4*)(gA0 + 4) = pA0[1];
            *(uint4*)(gC0) = pC0[0]; *(uint4*)(gC0 + 4) = pC0[1];
            *(uint4*)(gA1) = pA1[0]; *(uint4*)(gA1 + 4) = pA1[1];
            *(uint4*)(gC1) = pC1[0]; *(uint4*)(gC1 + 4) = pC1[1];
        }

        float acc[32];
        #pragma unroll
        for (int j = 0; j < 32; j++) acc[j] = 0.f;

        // ---- stage 1: EE @ M via ldmatrix fragments ----
        #pragma unroll
        for (int kt = 0; kt < 4; kt++) {
            uint32_t a0, a1, a2, a3;
            ldsm_x4(a0, a1, a2, a3, baseA + ((((kt << 1) + c01) ^ maskA) << 4));
            uint32_t bsw = (((kt << 1) + segB) ^ maskB) << 4;
            #pragma unroll
            for (int p = 0; p < 4; p++) {
                uint32_t b0, b1, b2, b3;
                ldsm_x4(b0, b1, b2, b3, baseB1 + p * 2048 + bsw);
                mma_f16(acc[(2*p)*4], acc[(2*p)*4+1], acc[(2*p)*4+2], acc[(2*p)*4+3],
                        a0, a1, a2, a3, b0, b1);
                mma_f16(acc[(2*p+1)*4], acc[(2*p+1)*4+1], acc[(2*p+1)*4+2], acc[(2*p+1)*4+3],
                        a0, a1, a2, a3, b2, b3);
            }
        }
        // ---- add gathers, relu, pack H into swizzled sEE ----
        #pragma unroll
        for (int nt = 0; nt < 8; nt++) {
            float2 fa0 = __half22float2(*(const __half2*)&gA0[nt]);
            float2 fc0 = __half22float2(*(const __half2*)&gC0[nt]);
            float2 fa1 = __half22float2(*(const __half2*)&gA1[nt]);
            float2 fc1 = __half22float2(*(const __half2*)&gC1[nt]);
            acc[nt*4+0] += fa0.x + fc0.x; acc[nt*4+1] += fa0.y + fc0.y;
            acc[nt*4+2] += fa1.x + fc1.x; acc[nt*4+3] += fa1.y + fc1.y;
        }
        __syncwarp();                    // warp done reading its EE rows
        #pragma unroll
        for (int nt = 0; nt < 8; nt++) {
            int cswz = (nt ^ g) << 4;
            *(__half2*)(hp1 + cswz) = __floats2half2_rn(fmaxf(acc[nt*4+0], 0.f),
                                                        fmaxf(acc[nt*4+1], 0.f));
            *(__half2*)(hp2 + cswz) = __floats2half2_rn(fmaxf(acc[nt*4+2], 0.f),
                                                        fmaxf(acc[nt*4+3], 0.f));
        }
        __syncwarp();                    // H visible to whole warp

        // ---- prefetch next tile (hidden under stage 2) ----
        int nxt = tile + gridDim.x;
        if (nxt < NTILES) {
            int e0n = nxt * 128;
            #pragma unroll
            for (int j = 0; j < 8; j++) {
                int i = t + 256 * j;
                pv[j] = ((const float4*)edgeEmb)[(size_t)(e0n + (i >> 4)) * 16 + (i & 15)];
            }
            if (t < 128) { ih = edgeIndex[e0n + t]; itl = edgeIndex[NE + e0n + t]; }
        }

        // ---- stage 2: z = relu(H @ W2 + b2); logit = z.Wh ----
        // hoist A (H) fragments once for both halves
        uint32_t ha[16];
        #pragma unroll
        for (int kt = 0; kt < 4; kt++) {
            ldsm_x4(ha[kt*4+0], ha[kt*4+1], ha[kt*4+2], ha[kt*4+3],
                    baseA + ((((kt << 1) + c01) ^ maskA) << 4));
        }
        float p0 = 0.f, p1 = 0.f;
        #pragma unroll
        for (int half = 0; half < 2; half++) {
            int cbase = half * 64;
            float acc2[32];
            #pragma unroll
            for (int nt = 0; nt < 8; nt++) {
                float bz0 = sb2[cbase + nt * 8 + tig2];
                float bz1 = sb2[cbase + nt * 8 + tig2 + 1];
                acc2[nt*4+0] = bz0; acc2[nt*4+1] = bz1;
                acc2[nt*4+2] = bz0; acc2[nt*4+3] = bz1;
            }
            #pragma unroll
            for (int kt = 0; kt < 4; kt++) {
                uint32_t bsw = (((kt << 1) + segB) ^ maskB) << 4;
                #pragma unroll
                for (int p = 0; p < 4; p++) {
                    uint32_t b0, b1, b2, b3;
                    ldsm_x4(b0, b1, b2, b3, baseB2 + half * 8192 + p * 2048 + bsw);
                    mma_f16(acc2[(2*p)*4], acc2[(2*p)*4+1], acc2[(2*p)*4+2], acc2[(2*p)*4+3],
                            ha[kt*4+0], ha[kt*4+1], ha[kt*4+2], ha[kt*4+3], b0, b1);
                    mma_f16(acc2[(2*p+1)*4], acc2[(2*p+1)*4+1], acc2[(2*p+1)*4+2], acc2[(2*p+1)*4+3],
                            ha[kt*4+0], ha[kt*4+1], ha[kt*4+2], ha[kt*4+3], b2, b3);
                }
            }
            #pragma unroll
            for (int nt = 0; nt < 8; nt++) {
                float w0 = sWh[cbase + nt * 8 + tig2];
                float w1 = sWh[cbase + nt * 8 + tig2 + 1];
                p0 += fmaxf(acc2[nt*4+0], 0.f) * w0 + fmaxf(acc2[nt*4+1], 0.f) * w1;
                p1 += fmaxf(acc2[nt*4+2], 0.f) * w0 + fmaxf(acc2[nt*4+3], 0.f) * w1;
            }
        }
        p0 += __shfl_xor_sync(0xffffffffu, p0, 1);
        p0 += __shfl_xor_sync(0xffffffffu, p0, 2);
        p1 += __shfl_xor_sync(0xffffffffu, p1, 1);
        p1 += __shfl_xor_sync(0xffffffffu, p1, 2);
        if (tig == 0) {
            out[e0 + rA]     = 1.f / (1.f + __expf(-(p0 + bhv)));
            out[e0 + rA + 8] = 1.f / (1.f + __expf(-(p1 + bhv)));
        }
    }
}

// ---------------- launch ----------------
extern "C" void kernel_launch(void* const* d_in, const int* in_sizes, int n_in,
                              void* d_out, int out_size) {
    const float* question_emb = (const float*)d_in[0];
    const float* node_emb     = (const float*)d_in[1];
    const float* edge_emb     = (const float*)d_in[2];
    const int*   edge_index   = (const int*)  d_in[3];
    const int*   node_batch   = (const int*)  d_in[4];
    const float* Wq = (const float*)d_in[5];
    const float* bq = (const float*)d_in[6];
    const float* We = (const float*)d_in[7];
    const float* be = (const float*)d_in[8];
    const float* Wr = (const float*)d_in[9];
    const float* br = (const float*)d_in[10];
    const float* W1 = (const float*)d_in[11];
    const float* b1 = (const float*)d_in[12];
    const float* W2 = (const float*)d_in[13];
    const float* b2 = (const float*)d_in[14];
    const float* Wh = (const float*)d_in[15];
    const float* bh = (const float*)d_in[16];
    float* out = (float*)d_out;

    prep_kernel<<<42, 256>>>(question_emb, Wq, bq, We, be, Wr, br, W1, b1, W2);
    node_mma_kernel<<<(NN + 127) / 128, 256>>>(node_emb, node_batch);

    cudaFuncSetAttribute(edge_kernel, cudaFuncAttributeMaxDynamicSharedMemorySize, SME_BYTES);
    edge_kernel<<<296, 256, SME_BYTES>>>(edge_emb, edge_index, b2, Wh, bh, out);
}

// round 17
// speedup vs baseline: 1.4624x; 1.4624x over previous
#include <cuda_runtime.h>
#include <cuda_fp16.h>
#include <math.h>
#include <stdint.h>

#define EMB 64
#define HID 128
#define NN  50000
#define NE  800000
#define NQ  64
#define NTILES (NE / 128)

// ---------------- scratch (static device globals; no allocation) ----------------
__device__ float   g_qr[NQ * EMB];        // q_repr = qe@Wq + bq
__device__ float   g_Aq[NQ * EMB];        // q_repr @ W1a
__device__ float   g_M [EMB * EMB];       // Wr @ W1c
__device__ float   g_Mb[EMB * EMB];       // We @ W1b
__device__ float   g_Md[EMB * EMB];       // We @ W1d
__device__ float   g_biasAB[EMB];         // b1 + be@W1b + br@W1c
__device__ float   g_biasC [EMB];         // be@W1d
// fp16 node tables in gather-native layout: row n has 32 half2; position tig*8+nt
__device__ __half2 g_ABnh[NN * 32];
__device__ __half2 g_Cnh [NN * 32];
__device__ __half2 g_Mt  [EMB * 32];      // M  as [n][k] fp16, k-contiguous (64 rows x 128B)
__device__ __half2 g_W2t [HID * 32];      // W2 as [n][k] fp16, k-contiguous (128 rows x 128B)
__device__ __half2 g_MbMdt[2 * EMB * 32]; // permuted layout for node kernel (rows 0..63 Mb, 64..127 Md)

// ---------------- helpers ----------------
__device__ __forceinline__ void mma_f16(float& c0, float& c1, float& c2, float& c3,
                                        uint32_t a0, uint32_t a1, uint32_t a2, uint32_t a3,
                                        uint32_t b0, uint32_t b1) {
    asm volatile("mma.sync.aligned.m16n8k16.row.col.f32.f16.f16.f32 "
                 "{%0,%1,%2,%3}, {%4,%5,%6,%7}, {%8,%9}, {%0,%1,%2,%3};\n"
                 : "+f"(c0), "+f"(c1), "+f"(c2), "+f"(c3)
                 : "r"(a0), "r"(a1), "r"(a2), "r"(a3), "r"(b0), "r"(b1));
}
__device__ __forceinline__ void ldsm_x4(uint32_t& r0, uint32_t& r1, uint32_t& r2, uint32_t& r3,
                                        uint32_t addr) {
    asm volatile("ldmatrix.sync.aligned.m8n8.x4.shared.b16 {%0,%1,%2,%3}, [%4];"
                 : "=r"(r0), "=r"(r1), "=r"(r2), "=r"(r3) : "r"(addr));
}
// permuted position for node-kernel layout
__device__ __forceinline__ int permp(int j) {
    int c = j >> 3, p = j & 7;
    return (c << 3) | ((p & 3) << 1) | (p >> 2);
}

// ---------------- prep 0: q_repr (coalesced along j across lanes) ----------------
__global__ void prep0_kernel(const float* __restrict__ qe,
                             const float* __restrict__ Wq,
                             const float* __restrict__ bq) {
    int idx = blockIdx.x * 256 + threadIdx.x;
    int q = idx >> 6, j = idx & 63;
    float s = bq[j];
    #pragma unroll 8
    for (int i = 0; i < EMB; i++) s += qe[q * EMB + i] * Wq[i * EMB + j];
    g_qr[idx] = s;
}

// ---------------- prep 1: folded matrices + biases (fp32, coalesced) ----------------
__global__ void prep1_kernel(const float* __restrict__ We,
                             const float* __restrict__ be,
                             const float* __restrict__ Wr,
                             const float* __restrict__ br,
                             const float* __restrict__ W1,
                             const float* __restrict__ b1) {
    int b = blockIdx.x;
    if (b < 64) {
        int m   = b >> 4;
        int idx = (b & 15) * 256 + threadIdx.x;
        int k = idx >> 6, j = idx & 63;
        float s = 0.f;
        if (m == 0) {
            #pragma unroll 8
            for (int i = 0; i < EMB; i++) s += g_qr[k * EMB + i] * W1[i * EMB + j];
            g_Aq[idx] = s;
        } else if (m == 1) {
            #pragma unroll 8
            for (int i = 0; i < EMB; i++) s += Wr[k * EMB + i] * W1[(128 + i) * EMB + j];
            g_M[idx] = s;
        } else if (m == 2) {
            #pragma unroll 8
            for (int i = 0; i < EMB; i++) s += We[k * EMB + i] * W1[(64 + i) * EMB + j];
            g_Mb[idx] = s;
        } else {
            #pragma unroll 8
            for (int i = 0; i < EMB; i++) s += We[k * EMB + i] * W1[(192 + i) * EMB + j];
            g_Md[idx] = s;
        }
    } else {
        if (threadIdx.x < EMB) {
            int j = threadIdx.x;
            float sAB = b1[j], sC = 0.f;
            #pragma unroll 8
            for (int i = 0; i < EMB; i++) {
                sAB += be[i] * W1[(64 + i) * EMB + j] + br[i] * W1[(128 + i) * EMB + j];
                sC  += be[i] * W1[(192 + i) * EMB + j];
            }
            g_biasAB[j] = sAB;
            g_biasC[j]  = sC;
        }
    }
}

// ---------------- prep 2: fp16 weight layouts from fp32 intermediates ----------------
__global__ void prep2_kernel(const float* __restrict__ W2) {
    int idx = blockIdx.x * 256 + threadIdx.x;   // 40 blocks -> 10240
    if (idx < 2048) {            // g_Mt plain [n][k]
        int n = idx >> 5, kp = idx & 31;
        g_Mt[idx] = __floats2half2_rn(g_M[(2 * kp) * EMB + n], g_M[(2 * kp + 1) * EMB + n]);
    } else if (idx < 6144) {     // g_W2t plain [n][k]
        int i2 = idx - 2048;
        int n = i2 >> 5, kp = i2 & 31;
        g_W2t[i2] = __floats2half2_rn(W2[(2 * kp) * HID + n], W2[(2 * kp + 1) * HID + n]);
    } else {                     // g_MbMdt permuted (node kernel)
        int i2 = idx - 6144;
        int n = i2 >> 5, pos = i2 & 31;
        int c = pos >> 3, q = pos & 7;
        int p = (q >> 1) + ((q & 1) << 2);
        int k0 = (c << 4) + (p << 1);
        const float* src = (n < 64) ? g_Mb : g_Md;
        int nn = n & 63;
        g_MbMdt[i2] = __floats2half2_rn(src[k0 * EMB + nn], src[(k0 + 1) * EMB + nn]);
    }
}

// ---------------- node kernel: fp16 mma, two 32-acc passes (3 blocks/SM) ----------------
__global__ __launch_bounds__(256, 3) void node_mma_kernel(const float* __restrict__ nodeEmb,
                                                          const int*   __restrict__ nodeBatch) {
    __shared__ __half2 sNE[128 * 40];
    __shared__ __half2 sW [128 * 40];

    int t = threadIdx.x;
    int n0 = blockIdx.x * 128;

    for (int i = t; i < 4096; i += 256) sW[(i >> 5) * 40 + (i & 31)] = g_MbMdt[i];
    #pragma unroll
    for (int j = 0; j < 8; j++) {
        int i = t + 256 * j;
        int r = i >> 4, q = i & 15;
        int n = n0 + r;
        float4 v = (n < NN) ? ((const float4*)nodeEmb)[(size_t)n * 16 + q]
                            : make_float4(0.f, 0.f, 0.f, 0.f);
        __half2* row = &sNE[r * 40];
        row[permp(2 * q)]     = __floats2half2_rn(v.x, v.y);
        row[permp(2 * q + 1)] = __floats2half2_rn(v.z, v.w);
    }
    __syncthreads();

    int w = t >> 5, lane = t & 31;
    int g = lane >> 2, tig = lane & 3;
    int rA = w * 16 + g;
    int tig2 = tig << 1;

    const __half2* eeLo = &sNE[rA * 40 + tig2];
    const __half2* eeHi = &sNE[(rA + 8) * 40 + tig2];

    int nlo = n0 + rA, nhi = n0 + rA + 8;
    int qlo = (nlo < NN) ? nodeBatch[nlo] : 0;
    int qhi = (nhi < NN) ? nodeBatch[nhi] : 0;

    // ---- pass A: ABn = ne@Mb + biasAB + Aq ----
    {
        float acc[32];
        #pragma unroll
        for (int j = 0; j < 32; j++) acc[j] = 0.f;
        #pragma unroll
        for (int kt = 0; kt < 4; kt++) {
            int base = kt * 8;
            uint2 va = *(const uint2*)(eeLo + base);
            uint2 vb = *(const uint2*)(eeHi + base);
            #pragma unroll
            for (int nt = 0; nt < 8; nt++) {
                uint2 wb = *(const uint2*)(&sW[(nt * 8 + g) * 40 + base + tig2]);
                mma_f16(acc[nt*4], acc[nt*4+1], acc[nt*4+2], acc[nt*4+3],
                        va.x, vb.x, va.y, vb.y, wb.x, wb.y);
            }
        }
        __half2 blo[8], bhi[8];
        #pragma unroll
        for (int nt = 0; nt < 8; nt++) {
            int c = nt * 8 + tig2;
            float bA0 = g_biasAB[c], bA1 = g_biasAB[c + 1];
            blo[nt] = __floats2half2_rn(acc[nt*4+0] + bA0 + g_Aq[qlo * 64 + c],
                                        acc[nt*4+1] + bA1 + g_Aq[qlo * 64 + c + 1]);
            bhi[nt] = __floats2half2_rn(acc[nt*4+2] + bA0 + g_Aq[qhi * 64 + c],
                                        acc[nt*4+3] + bA1 + g_Aq[qhi * 64 + c + 1]);
        }
        if (nlo < NN) {
            __half2* dA = g_ABnh + (size_t)nlo * 32 + tig * 8;
            *(uint4*)(dA) = *(uint4*)(blo); *(uint4*)(dA + 4) = *(uint4*)(blo + 4);
        }
        if (nhi < NN) {
            __half2* dA = g_ABnh + (size_t)nhi * 32 + tig * 8;
            *(uint4*)(dA) = *(uint4*)(bhi); *(uint4*)(dA + 4) = *(uint4*)(bhi + 4);
        }
    }
    // ---- pass B: Cn = ne@Md + biasC ----
    {
        float acc[32];
        #pragma unroll
        for (int j = 0; j < 32; j++) acc[j] = 0.f;
        #pragma unroll
        for (int kt = 0; kt < 4; kt++) {
            int base = kt * 8;
            uint2 va = *(const uint2*)(eeLo + base);
            uint2 vb = *(const uint2*)(eeHi + base);
            #pragma unroll
            for (int nt = 0; nt < 8; nt++) {
                uint2 wb = *(const uint2*)(&sW[(64 + nt * 8 + g) * 40 + base + tig2]);
                mma_f16(acc[nt*4], acc[nt*4+1], acc[nt*4+2], acc[nt*4+3],
                        va.x, vb.x, va.y, vb.y, wb.x, wb.y);
            }
        }
        __half2 blo[8], bhi[8];
        #pragma unroll
        for (int nt = 0; nt < 8; nt++) {
            int c = nt * 8 + tig2;
            float bC0 = g_biasC[c], bC1 = g_biasC[c + 1];
            blo[nt] = __floats2half2_rn(acc[nt*4+0] + bC0, acc[nt*4+1] + bC1);
            bhi[nt] = __floats2half2_rn(acc[nt*4+2] + bC0, acc[nt*4+3] + bC1);
        }
        if (nlo < NN) {
            __half2* dC = g_Cnh + (size_t)nlo * 32 + tig * 8;
            *(uint4*)(dC) = *(uint4*)(blo); *(uint4*)(dC + 4) = *(uint4*)(blo + 4);
        }
        if (nhi < NN) {
            __half2* dC = g_Cnh + (size_t)nhi * 32 + tig * 8;
            *(uint4*)(dC) = *(uint4*)(bhi); *(uint4*)(dC + 4) = *(uint4*)(bhi + 4);
        }
    }
}

// ---------------- persistent edge kernel: SW128 + ldmatrix fragment path ----------------
// smem bytes: sEE 0..16384 (128 rows x 128B, swizzled; EE tile then H)
//             sM  16384..24576 | sW2 24576..40960 | sWh/sb2/sHT tail
#define OFF_M   16384
#define OFF_W2  24576
#define OFF_WHb 40960
#define SME_BYTES (40960 + 512 + 512 + 1024)

__global__ __launch_bounds__(256, 2) void edge_kernel(const float* __restrict__ edgeEmb,
                                                      const int*   __restrict__ edgeIndex,
                                                      const float* __restrict__ b2,
                                                      const float* __restrict__ Wh,
                                                      const float* __restrict__ bh,
                                                      float* __restrict__ out) {
    extern __shared__ char smE[];
    uint32_t sbs = (uint32_t)__cvta_generic_to_shared(smE);
    float* sWh = (float*)(smE + OFF_WHb);
    float* sb2 = (float*)(smE + OFF_WHb + 512);
    int*   sHT = (int*)  (smE + OFF_WHb + 1024);

    int t = threadIdx.x;

    // ---- copy weights into swizzled smem ONCE ----
    {
        const uint4* gm = (const uint4*)g_Mt;
        uint4* dm = (uint4*)(smE + OFF_M);
        for (int i = t; i < 512; i += 256) {
            int d = (i & ~7) | ((i & 7) ^ ((i >> 3) & 7));
            dm[d] = gm[i];
        }
        const uint4* gw = (const uint4*)g_W2t;
        uint4* dw = (uint4*)(smE + OFF_W2);
        for (int i = t; i < 1024; i += 256) {
            int d = (i & ~7) | ((i & 7) ^ ((i >> 3) & 7));
            dw[d] = gw[i];
        }
    }
    if (t < 128) { sWh[t] = Wh[t]; sb2[t] = b2[t]; }
    float bhv = bh[0];

    int w = t >> 5, lane = t & 31;
    int g = lane >> 2, tig = lane & 3;
    int rA = w * 16 + g;
    int tig2 = tig << 1;

    // staging offsets: thread's 8 chunks -> swizzled 8B slots
    int soff[8];
    #pragma unroll
    for (int j = 0; j < 8; j++) {
        int i = t + 256 * j;
        int r = i >> 4, q = i & 15;
        soff[j] = (r * 8 + ((q >> 1) ^ (r & 7))) * 16 + (q & 1) * 8;
    }

    // ldmatrix per-thread address components
    int laneRowA = w * 16 + (lane & 7) + ((lane >> 3) & 1) * 8;
    int c01   = (lane >> 4) & 1;
    int maskA = laneRowA & 7;
    uint32_t baseA = sbs + laneRowA * 128;
    int rBl   = ((lane >> 4) << 3) + (lane & 7);
    int segB  = (lane >> 3) & 1;
    int maskB = rBl & 7;
    uint32_t baseB1 = sbs + OFF_M  + rBl * 128;
    uint32_t baseB2 = sbs + OFF_W2 + rBl * 128;

    // H writeback pointers
    char* hp1 = smE + rA * 128 + tig * 4;
    char* hp2 = smE + (rA + 8) * 128 + tig * 4;

    // ---- prefetch first tile ----
    float4 pv[8];
    int ih = 0, itl = 0;
    int tile = blockIdx.x;
    if (tile < NTILES) {
        int e0 = tile * 128;
        #pragma unroll
        for (int j = 0; j < 8; j++) {
            int i = t + 256 * j;
            pv[j] = ((const float4*)edgeEmb)[(size_t)(e0 + (i >> 4)) * 16 + (i & 15)];
        }
        if (t < 128) { ih = edgeIndex[e0 + t]; itl = edgeIndex[NE + e0 + t]; }
    }

    for (; tile < NTILES; tile += gridDim.x) {
        int e0 = tile * 128;
        __syncthreads();                 // prior tile's smem reads done
        #pragma unroll
        for (int j = 0; j < 8; j++) {
            __half2 h0 = __floats2half2_rn(pv[j].x, pv[j].y);
            __half2 h1 = __floats2half2_rn(pv[j].z, pv[j].w);
            uint2 hv;
            hv.x = *(uint32_t*)&h0;
            hv.y = *(uint32_t*)&h1;
            *(uint2*)(smE + soff[j]) = hv;
        }
        if (t < 128) { sHT[t] = ih; sHT[128 + t] = itl; }
        __syncthreads();                 // tile visible

        // ---- issue node-table gathers (consumed AFTER stage 1) ----
        int h0i = sHT[rA],     t0i = sHT[128 + rA];
        int h1i = sHT[rA + 8], t1i = sHT[128 + rA + 8];
        uint32_t gA0[8], gC0[8], gA1[8], gC1[8];
        {
            const uint4* pA0 = (const uint4*)(g_ABnh + (size_t)h0i * 32 + tig * 8);
            const uint4* pC0 = (const uint4*)(g_Cnh  + (size_t)t0i * 32 + tig * 8);
            const uint4* pA1 = (const uint4*)(g_ABnh + (size_t)h1i * 32 + tig * 8);
            const uint4* pC1 = (const uint4*)(g_Cnh  + (size_t)t1i * 32 + tig * 8);
            *(uint4*)(gA0) = pA0[0]; *(uint4*)(gA0 + 4) = pA0[1];
            *(uint4*)(gC0) = pC0[0]; *(uint4*)(gC0 + 4) = pC0[1];
            *(uint4*)(gA1) = pA1[0]; *(uint4*)(gA1 + 4) = pA1[1];
            *(uint4*)(gC1) = pC1[0]; *(uint4*)(gC1 + 4) = pC1[1];
        }

        float acc[32];
        #pragma unroll
        for (int j = 0; j < 32; j++) acc[j] = 0.f;

        // ---- stage 1: EE @ M via ldmatrix fragments ----
        #pragma unroll
        for (int kt = 0; kt < 4; kt++) {
            uint32_t a0, a1, a2, a3;
            ldsm_x4(a0, a1, a2, a3, baseA + ((((kt << 1) + c01) ^ maskA) << 4));
            uint32_t bsw = (((kt << 1) + segB) ^ maskB) << 4;
            #pragma unroll
            for (int p = 0; p < 4; p++) {
                uint32_t b0, b1, b2, b3;
                ldsm_x4(b0, b1, b2, b3, baseB1 + p * 2048 + bsw);
                mma_f16(acc[(2*p)*4], acc[(2*p)*4+1], acc[(2*p)*4+2], acc[(2*p)*4+3],
                        a0, a1, a2, a3, b0, b1);
                mma_f16(acc[(2*p+1)*4], acc[(2*p+1)*4+1], acc[(2*p+1)*4+2], acc[(2*p+1)*4+3],
                        a0, a1, a2, a3, b2, b3);
            }
        }
        // ---- add gathers, relu, pack H into swizzled sEE ----
        #pragma unroll
        for (int nt = 0; nt < 8; nt++) {
            float2 fa0 = __half22float2(*(const __half2*)&gA0[nt]);
            float2 fc0 = __half22float2(*(const __half2*)&gC0[nt]);
            float2 fa1 = __half22float2(*(const __half2*)&gA1[nt]);
            float2 fc1 = __half22float2(*(const __half2*)&gC1[nt]);
            acc[nt*4+0] += fa0.x + fc0.x; acc[nt*4+1] += fa0.y + fc0.y;
            acc[nt*4+2] += fa1.x + fc1.x; acc[nt*4+3] += fa1.y + fc1.y;
        }
        __syncwarp();                    // warp done reading its EE rows
        #pragma unroll
        for (int nt = 0; nt < 8; nt++) {
            int cswz = (nt ^ g) << 4;
            *(__half2*)(hp1 + cswz) = __floats2half2_rn(fmaxf(acc[nt*4+0], 0.f),
                                                        fmaxf(acc[nt*4+1], 0.f));
            *(__half2*)(hp2 + cswz) = __floats2half2_rn(fmaxf(acc[nt*4+2], 0.f),
                                                        fmaxf(acc[nt*4+3], 0.f));
        }
        __syncwarp();                    // H visible to whole warp

        // ---- prefetch next tile (hidden under stage 2) ----
        int nxt = tile + gridDim.x;
        if (nxt < NTILES) {
            int e0n = nxt * 128;
            #pragma unroll
            for (int j = 0; j < 8; j++) {
                int i = t + 256 * j;
                pv[j] = ((const float4*)edgeEmb)[(size_t)(e0n + (i >> 4)) * 16 + (i & 15)];
            }
            if (t < 128) { ih = edgeIndex[e0n + t]; itl = edgeIndex[NE + e0n + t]; }
        }

        // ---- stage 2: z = relu(H @ W2 + b2); logit = z.Wh ----
        // hoist A (H) fragments once for both halves
        uint32_t ha[16];
        #pragma unroll
        for (int kt = 0; kt < 4; kt++) {
            ldsm_x4(ha[kt*4+0], ha[kt*4+1], ha[kt*4+2], ha[kt*4+3],
                    baseA + ((((kt << 1) + c01) ^ maskA) << 4));
        }
        float p0 = 0.f, p1 = 0.f;
        #pragma unroll
        for (int half = 0; half < 2; half++) {
            int cbase = half * 64;
            float acc2[32];
            #pragma unroll
            for (int nt = 0; nt < 8; nt++) {
                float bz0 = sb2[cbase + nt * 8 + tig2];
                float bz1 = sb2[cbase + nt * 8 + tig2 + 1];
                acc2[nt*4+0] = bz0; acc2[nt*4+1] = bz1;
                acc2[nt*4+2] = bz0; acc2[nt*4+3] = bz1;
            }
            #pragma unroll
            for (int kt = 0; kt < 4; kt++) {
                uint32_t bsw = (((kt << 1) + segB) ^ maskB) << 4;
                #pragma unroll
                for (int p = 0; p < 4; p++) {
                    uint32_t b0, b1, b2, b3;
                    ldsm_x4(b0, b1, b2, b3, baseB2 + half * 8192 + p * 2048 + bsw);
                    mma_f16(acc2[(2*p)*4], acc2[(2*p)*4+1], acc2[(2*p)*4+2], acc2[(2*p)*4+3],
                            ha[kt*4+0], ha[kt*4+1], ha[kt*4+2], ha[kt*4+3], b0, b1);
                    mma_f16(acc2[(2*p+1)*4], acc2[(2*p+1)*4+1], acc2[(2*p+1)*4+2], acc2[(2*p+1)*4+3],
                            ha[kt*4+0], ha[kt*4+1], ha[kt*4+2], ha[kt*4+3], b2, b3);
                }
            }
            #pragma unroll
            for (int nt = 0; nt < 8; nt++) {
                float w0 = sWh[cbase + nt * 8 + tig2];
                float w1 = sWh[cbase + nt * 8 + tig2 + 1];
                p0 += fmaxf(acc2[nt*4+0], 0.f) * w0 + fmaxf(acc2[nt*4+1], 0.f) * w1;
                p1 += fmaxf(acc2[nt*4+2], 0.f) * w0 + fmaxf(acc2[nt*4+3], 0.f) * w1;
            }
        }
        p0 += __shfl_xor_sync(0xffffffffu, p0, 1);
        p0 += __shfl_xor_sync(0xffffffffu, p0, 2);
        p1 += __shfl_xor_sync(0xffffffffu, p1, 1);
        p1 += __shfl_xor_sync(0xffffffffu, p1, 2);
        if (tig == 0) {
            out[e0 + rA]     = 1.f / (1.f + __expf(-(p0 + bhv)));
            out[e0 + rA + 8] = 1.f / (1.f + __expf(-(p1 + bhv)));
        }
    }
}

// ---------------- launch ----------------
extern "C" void kernel_launch(void* const* d_in, const int* in_sizes, int n_in,
                              void* d_out, int out_size) {
    const float* question_emb = (const float*)d_in[0];
    const float* node_emb     = (const float*)d_in[1];
    const float* edge_emb     = (const float*)d_in[2];
    const int*   edge_index   = (const int*)  d_in[3];
    const int*   node_batch   = (const int*)  d_in[4];
    const float* Wq = (const float*)d_in[5];
    const float* bq = (const float*)d_in[6];
    const float* We = (const float*)d_in[7];
    const float* be = (const float*)d_in[8];
    const float* Wr = (const float*)d_in[9];
    const float* br = (const float*)d_in[10];
    const float* W1 = (const float*)d_in[11];
    const float* b1 = (const float*)d_in[12];
    const float* W2 = (const float*)d_in[13];
    const float* b2 = (const float*)d_in[14];
    const float* Wh = (const float*)d_in[15];
    const float* bh = (const float*)d_in[16];
    float* out = (float*)d_out;

    prep0_kernel<<<16, 256>>>(question_emb, Wq, bq);
    prep1_kernel<<<65, 256>>>(We, be, Wr, br, W1, b1);
    prep2_kernel<<<40, 256>>>(W2);
    node_mma_kernel<<<(NN + 127) / 128, 256>>>(node_emb, node_batch);

    cudaFuncSetAttribute(edge_kernel, cudaFuncAttributeMaxDynamicSharedMemorySize, SME_BYTES);
    edge_kernel<<<296, 256, SME_BYTES>>>(edge_emb, edge_index, b2, Wh, bh, out);
}